// round 7
// baseline (speedup 1.0000x reference)
#include <cuda_runtime.h>
#include <cstdint>

// out[n][c] = in[n][c] + glob[batch[n]][c]
// N = 1,000,000, C = 128, B = 8, fp32.  ~1.03 GB streamed.
//
// R7: 256-bit vector ld/st (sm_100+ v8.b32), each thread owns 8 contiguous
//     floats (32B aligned). ILP=4 vec8 per thread, unguarded fast path.

static constexpr int C_VEC8  = 128 / 8;  // 16 vec8 per row
static constexpr int UNROLL  = 4;
static constexpr int THREADS = 256;

struct V8 { float v[8]; };

__device__ __forceinline__ V8 ld_v8_cs(const float* p) {
    V8 r;
    uint32_t a, b, c, d, e, f, g, h;
    asm volatile("ld.global.cs.v8.b32 {%0,%1,%2,%3,%4,%5,%6,%7}, [%8];"
                 : "=r"(a), "=r"(b), "=r"(c), "=r"(d),
                   "=r"(e), "=r"(f), "=r"(g), "=r"(h)
                 : "l"(p));
    r.v[0] = __uint_as_float(a); r.v[1] = __uint_as_float(b);
    r.v[2] = __uint_as_float(c); r.v[3] = __uint_as_float(d);
    r.v[4] = __uint_as_float(e); r.v[5] = __uint_as_float(f);
    r.v[6] = __uint_as_float(g); r.v[7] = __uint_as_float(h);
    return r;
}

__device__ __forceinline__ void st_v8_cs(float* p, const V8& r) {
    asm volatile("st.global.cs.v8.b32 [%0], {%1,%2,%3,%4,%5,%6,%7,%8};"
                 :: "l"(p),
                    "r"(__float_as_uint(r.v[0])), "r"(__float_as_uint(r.v[1])),
                    "r"(__float_as_uint(r.v[2])), "r"(__float_as_uint(r.v[3])),
                    "r"(__float_as_uint(r.v[4])), "r"(__float_as_uint(r.v[5])),
                    "r"(__float_as_uint(r.v[6])), "r"(__float_as_uint(r.v[7]))
                 : "memory");
}

// Fast path: 256-bit ops, no bounds checks (exact divisibility).
__global__ __launch_bounds__(THREADS)
void sgb_v8_kernel(const float* __restrict__ in,
                   const float4* __restrict__ glob,
                   const int*   __restrict__ bidx,
                   float*       __restrict__ out) {
    unsigned base = blockIdx.x * (THREADS * UNROLL) + threadIdx.x;  // vec8 index

    V8  a[UNROLL];
    int b[UNROLL];

    // Front-batch: 4x LDG.256 (stream) + 4x LDG.32 (bidx, warp-uniform per 16 lanes).
    #pragma unroll
    for (int u = 0; u < UNROLL; u++) {
        unsigned i = base + u * THREADS;              // vec8 index
        a[u] = ld_v8_cs(in + (size_t)i * 8);
        b[u] = __ldg(&bidx[i >> 4]);                  // row = i/16
    }

    #pragma unroll
    for (int u = 0; u < UNROLL; u++) {
        unsigned i = base + u * THREADS;
        unsigned lane8 = i & 15;                      // vec8 within row
        const float4* gp = glob + (unsigned)b[u] * 32 + lane8 * 2;  // 4 KB, L1-hit
        float4 g0 = __ldg(gp);
        float4 g1 = __ldg(gp + 1);
        V8 r;
        r.v[0] = a[u].v[0] + g0.x;  r.v[1] = a[u].v[1] + g0.y;
        r.v[2] = a[u].v[2] + g0.z;  r.v[3] = a[u].v[3] + g0.w;
        r.v[4] = a[u].v[4] + g1.x;  r.v[5] = a[u].v[5] + g1.y;
        r.v[6] = a[u].v[6] + g1.z;  r.v[7] = a[u].v[7] + g1.w;
        st_v8_cs(out + (size_t)i * 8, r);
    }
}

// Guarded fallback: float4 path (handles non-divisible sizes).
__global__ __launch_bounds__(THREADS)
void sgb_f4_kernel(const float4* __restrict__ in,
                   const float4* __restrict__ glob,
                   const int*    __restrict__ bidx,
                   float4*       __restrict__ out,
                   unsigned n_vec) {
    unsigned base = blockIdx.x * (THREADS * UNROLL) + threadIdx.x;
    #pragma unroll
    for (int u = 0; u < UNROLL; u++) {
        unsigned i = base + u * THREADS;
        if (i < n_vec) {
            float4 a = __ldcs(&in[i]);
            int bb = __ldg(&bidx[i >> 5]);
            float4 g = __ldg(&glob[(unsigned)bb * 32 + (i & 31)]);
            float4 r;
            r.x = a.x + g.x; r.y = a.y + g.y; r.z = a.z + g.z; r.w = a.w + g.w;
            __stcs(&out[i], r);
        }
    }
}

extern "C" void kernel_launch(void* const* d_in, const int* in_sizes, int n_in,
                              void* d_out, int out_size) {
    const float*  in   = (const float*)d_in[0];    // input_features        [N, C]
    const float4* glob = (const float4*)d_in[1];   // input_features_global [B, C]
    const int*    bidx = (const int*)d_in[2];      // batch_indices         [N]

    long long n_elems = (long long)in_sizes[0];    // N * C = 128M

    unsigned per_block8 = THREADS * UNROLL;        // vec8 per block = 1024
    if (n_elems % 8 == 0 && (n_elems / 8) % per_block8 == 0) {
        unsigned n_v8 = (unsigned)(n_elems / 8);   // 16M
        unsigned blocks = n_v8 / per_block8;       // 16384
        sgb_v8_kernel<<<blocks, THREADS>>>(in, glob, bidx, (float*)d_out);
    } else {
        unsigned n_vec = (unsigned)(n_elems / 4);
        unsigned per_block = THREADS * UNROLL;
        unsigned blocks = (n_vec + per_block - 1) / per_block;
        sgb_f4_kernel<<<blocks, THREADS>>>((const float4*)in, glob, bidx,
                                           (float4*)d_out, n_vec);
    }
}

// round 8
// speedup vs baseline: 1.0171x; 1.0171x over previous
#include <cuda_runtime.h>

// out[n][c] = in[n][c] + glob[batch[n]][c]
// N = 1,000,000, C = 128, B = 8, fp32.  ~1.03 GB streamed.
//
// FINAL (R6 config, best measured): flat grid, 512-thread blocks, ILP=4
// front-batched LDG.128 with evict-first hints, unguarded fast path,
// 32-bit indexing. Five structurally different variants all converge to
// ~144 us kernel time / ~85% DRAM => HBM mixed-stream ceiling reached.

static constexpr int C_VEC   = 128 / 4;  // 32 float4 per row
static constexpr int UNROLL  = 4;
static constexpr int THREADS = 512;

template <bool GUARD>
__global__ __launch_bounds__(THREADS)
void sparse_global_broadcast_kernel(const float4* __restrict__ in,
                                    const float4* __restrict__ glob,
                                    const int*    __restrict__ bidx,
                                    float4*       __restrict__ out,
                                    unsigned n_vec) {
    unsigned base = blockIdx.x * (THREADS * UNROLL) + threadIdx.x;

    float4 a[UNROLL];
    int    b[UNROLL];

    // Front-batch all independent loads: 4x LDG.128 (stream) + 4x LDG.32 (bidx).
    #pragma unroll
    for (int u = 0; u < UNROLL; u++) {
        unsigned i = base + u * THREADS;
        if (!GUARD || i < n_vec) {
            a[u] = __ldcs(&in[i]);            // evict-first streaming load
            b[u] = __ldg(&bidx[i >> 5]);      // warp-uniform row index, cached
        }
    }

    #pragma unroll
    for (int u = 0; u < UNROLL; u++) {
        unsigned i = base + u * THREADS;
        if (!GUARD || i < n_vec) {
            unsigned lane = i & 31;
            float4 g = __ldg(&glob[(unsigned)b[u] * C_VEC + lane]);  // 4 KB, L1-hit
            float4 r;
            r.x = a[u].x + g.x;
            r.y = a[u].y + g.y;
            r.z = a[u].z + g.z;
            r.w = a[u].w + g.w;
            __stcs(&out[i], r);               // streaming store
        }
    }
}

extern "C" void kernel_launch(void* const* d_in, const int* in_sizes, int n_in,
                              void* d_out, int out_size) {
    const float4* in   = (const float4*)d_in[0];   // input_features        [N, C]
    const float4* glob = (const float4*)d_in[1];   // input_features_global [B, C]
    const int*    bidx = (const int*)d_in[2];      // batch_indices         [N]

    float4* out = (float4*)d_out;

    unsigned n_vec = (unsigned)((long long)in_sizes[0] / 4);   // N*C/4 = 32M
    unsigned per_block = THREADS * UNROLL;                      // 2048
    unsigned blocks = (n_vec + per_block - 1) / per_block;      // 15625

    if (n_vec % per_block == 0) {
        sparse_global_broadcast_kernel<false><<<blocks, THREADS>>>(in, glob, bidx, out, n_vec);
    } else {
        sparse_global_broadcast_kernel<true><<<blocks, THREADS>>>(in, glob, bidx, out, n_vec);
    }
}